// round 5
// baseline (speedup 1.0000x reference)
#include <cuda_runtime.h>
#include <cstdint>
#include <cstddef>

// Problem shape (fixed by the reference setup_inputs)
#define BB 64
#define TT 2048
#define NN 32
#define DD 12           // cp.async ring stages (distance 11 x ~160cyc >> DRAM lat)
#define NTH 128
#define KNINF (-1e4f)
#define NEG_BIG (-3.402823466e38f)
#define LSEG 128
#define MAXSEG (TT / LSEG)   // 16

struct __align__(16) Smem {
    float tiles[DD][NN * NN];        // 48 KB, swizzled rows
    float alpha[2][NN];              // double-buffered alpha
    unsigned char back[TT][NN];      // 64 KB backpointers
    unsigned char M[MAXSEG][NN];     // composed segment maps
    int entry[MAXSEG];               // tag at hi of each segment
    int misc[8];                     // [0..3] warp counts, [5] last_tag
};

__device__ __forceinline__ void cp16(unsigned dst, const void* src) {
    asm volatile("cp.async.cg.shared.global [%0], [%1], 16;" :: "r"(dst), "l"(src));
}
__device__ __forceinline__ void cp_commit() { asm volatile("cp.async.commit_group;"); }
template<int Nn> __device__ __forceinline__ void cp_wait() {
    asm volatile("cp.async.wait_group %0;" :: "n"(Nn));
}

__global__ void __launch_bounds__(NTH, 1)
viterbi_kernel(const float* __restrict__ lp, const int* __restrict__ mask,
               const int* __restrict__ startc, const int* __restrict__ endc,
               const int* __restrict__ transc, float* __restrict__ out)
{
    extern __shared__ __align__(16) char smraw[];
    Smem& sm = *reinterpret_cast<Smem*>(smraw);
    const int b    = blockIdx.x;
    const int tid  = threadIdx.x;
    const int w    = tid >> 5;        // warp id: owns columns j = 8w..8w+7
    const int lane = tid & 31;
    const int jloc = lane & 7;
    const int igrp = lane >> 3;       // i-group: i = 8*igrp .. 8*igrp+7
    const int j    = w * 8 + jloc;
    const int i0   = igrp * 8;
    const unsigned colmask = 0x01010101u << jloc;   // the 4 lanes of column j

    // ---- sequence length (mask is prefix-true) ----
    int cnt = 0;
    #pragma unroll
    for (int t = tid; t < TT; t += NTH) cnt += (mask[b * TT + t] != 0);
    #pragma unroll
    for (int o = 16; o; o >>= 1) cnt += __shfl_xor_sync(0xffffffffu, cnt, o);
    if (lane == 0) sm.misc[w] = cnt;
    __syncthreads();
    const int len  = sm.misc[0] + sm.misc[1] + sm.misc[2] + sm.misc[3];
    const int last = len - 1;

    // ---- per-thread constants ----
    float tr[8];
    #pragma unroll
    for (int k = 0; k < 8; k++)
        tr[k] = transc[(i0 + k) * NN + j] ? 0.0f : KNINF;
    const float sp_j = startc[j] ? 0.0f : KNINF;
    const float ep_j = endc[j]   ? 0.0f : KNINF;

    const float* lpb = lp + (size_t)b * TT * NN * NN;

    // ---- cp.async slice: each thread copies two 16B chunks per tile ----
    // Swizzle: 16B-chunk cc of row r stored at byte r*128 + ((16*cc + 32*(r>>3)) & 127)
    const int c2  = tid * 2;
    const int row = c2 >> 3;
    const int cc  = c2 & 7;
    const unsigned swz = (unsigned)((row >> 3) << 5);
    const unsigned dA  = (unsigned)(row * 128) + (((unsigned)(cc * 16)      + swz) & 127u);
    const unsigned dB  = (unsigned)(row * 128) + (((unsigned)(cc * 16 + 16) + swz) & 127u);
    const float* srcBase = lpb + row * NN + cc * 4;
    const unsigned tilesBase = (unsigned)__cvta_generic_to_shared(&sm.tiles[0][0]);
    // reader: element (i = i0+k, j) lives at tiles[stage][ (i0+k)*32 + cOff ]
    const int cOff = (j + 8 * igrp) & 31;

    // ---- prologue: issue tiles 0..DD-2 (one commit group per tile slot) ----
    for (int k = 0; k < DD - 1; k++) {
        if (k <= last) {
            unsigned sb = tilesBase + (unsigned)(k * (NN * NN * 4));
            const float* s0 = srcBase + (size_t)k * NN * NN;
            cp16(sb + dA, s0);
            cp16(sb + dB, s0 + 4);
        }
        cp_commit();
    }

    // ---- t = 0: alpha0[j] = max_i lp[0,i,j] + start_pen (+ end_pen if len==1) ----
    cp_wait<DD - 2>();
    __syncthreads();
    {
        const int ft = DD - 1;
        if (ft <= last) {
            unsigned sb = tilesBase + (unsigned)((ft % DD) * (NN * NN * 4));
            const float* s0 = srcBase + (size_t)ft * NN * NN;
            cp16(sb + dA, s0);
            cp16(sb + dB, s0 + 4);
        }
        cp_commit();

        const float* tile = sm.tiles[0];
        float best = NEG_BIG;
        #pragma unroll
        for (int k = 0; k < 8; k++)
            best = fmaxf(best, tile[(i0 + k) * NN + cOff]);
        best = fmaxf(best, __shfl_xor_sync(0xffffffffu, best, 8));
        best = fmaxf(best, __shfl_xor_sync(0xffffffffu, best, 16));
        if (igrp == 0) {
            float e = (last == 0) ? ep_j : 0.0f;
            sm.alpha[0][j] = (best + sp_j) + e;   // const-in-i shift commutes with max
        }
    }

    // ---- main forward loop: one __syncthreads per step ----
    // Critical path carries VALUES only; backpointer recovery is deferred one
    // iteration into the LDS shadow of the next step.
    int p = 0;                 // alpha[p] holds alpha_{t-1}
    float ps[8];               // previous step's 8 sums (for deferred argmax)
    float plocal = 0.0f;       // previous lane-local max
    float pbestf = 0.0f;       // previous column-final max

    for (int t = 1; t <= last; t++) {
        cp_wait<DD - 2>();
        __syncthreads();   // tile t visible; alpha(t-1) visible; stage (t-1)%DD free

        const int ft = t + DD - 1;
        if (ft <= last) {
            unsigned sb = tilesBase + (unsigned)((ft % DD) * (NN * NN * 4));
            const float* s0 = srcBase + (size_t)ft * NN * NN;
            cp16(sb + dA, s0);
            cp16(sb + dB, s0 + 4);
        }
        cp_commit();

        // issue tile + alpha loads first (29-cyc shadow follows)
        const float* tile = sm.tiles[t % DD];
        float tv[8];
        #pragma unroll
        for (int k = 0; k < 8; k++) tv[k] = tile[(i0 + k) * NN + cOff];
        const float4 av0 = *reinterpret_cast<const float4*>(&sm.alpha[p][i0]);
        const float4 av1 = *reinterpret_cast<const float4*>(&sm.alpha[p][i0 + 4]);
        const float a[8] = {av0.x, av0.y, av0.z, av0.w, av1.x, av1.y, av1.z, av1.w};

        // ---- deferred backpointer for step t-1 (fills the load shadow) ----
        if (t > 1) {
            int bi = 7;
            #pragma unroll
            for (int k = 7; k >= 0; k--) if (ps[k] == plocal) bi = k;  // first-max in k
            bi += i0;
            unsigned ball = __ballot_sync(0xffffffffu, plocal == pbestf);
            int src = __ffs(ball & colmask) - 1;      // lowest igrp = smallest i
            int bif = __shfl_sync(0xffffffffu, bi, src);
            if (igrp == 0) sm.back[t - 1][j] = (unsigned char)bif;
        }

        // ---- value-only alpha update (exact FP order preserved from ref) ----
        float s0_, s1_, s2_, s3_, s4_, s5_, s6_, s7_;
        if (t != last) {
            s0_ = (tv[0] + tr[0]) + a[0];  s1_ = (tv[1] + tr[1]) + a[1];
            s2_ = (tv[2] + tr[2]) + a[2];  s3_ = (tv[3] + tr[3]) + a[3];
            s4_ = (tv[4] + tr[4]) + a[4];  s5_ = (tv[5] + tr[5]) + a[5];
            s6_ = (tv[6] + tr[6]) + a[6];  s7_ = (tv[7] + tr[7]) + a[7];
        } else {   // peeled end step: ((phi+tr)+ep)+alpha
            s0_ = ((tv[0] + tr[0]) + ep_j) + a[0];  s1_ = ((tv[1] + tr[1]) + ep_j) + a[1];
            s2_ = ((tv[2] + tr[2]) + ep_j) + a[2];  s3_ = ((tv[3] + tr[3]) + ep_j) + a[3];
            s4_ = ((tv[4] + tr[4]) + ep_j) + a[4];  s5_ = ((tv[5] + tr[5]) + ep_j) + a[5];
            s6_ = ((tv[6] + tr[6]) + ep_j) + a[6];  s7_ = ((tv[7] + tr[7]) + ep_j) + a[7];
        }
        float m0 = fmaxf(s0_, s1_), m1 = fmaxf(s2_, s3_);
        float m2 = fmaxf(s4_, s5_), m3 = fmaxf(s6_, s7_);
        float n0 = fmaxf(m0, m1),   n1 = fmaxf(m2, m3);
        float local = fmaxf(n0, n1);
        float bf = local;
        bf = fmaxf(bf, __shfl_xor_sync(0xffffffffu, bf, 8));
        bf = fmaxf(bf, __shfl_xor_sync(0xffffffffu, bf, 16));
        if (igrp == 0) sm.alpha[p ^ 1][j] = bf;

        ps[0]=s0_; ps[1]=s1_; ps[2]=s2_; ps[3]=s3_;
        ps[4]=s4_; ps[5]=s5_; ps[6]=s6_; ps[7]=s7_;
        plocal = local; pbestf = bf;
        p ^= 1;
    }

    // flush last step's backpointer
    if (last >= 1) {
        int bi = 7;
        #pragma unroll
        for (int k = 7; k >= 0; k--) if (ps[k] == plocal) bi = k;
        bi += i0;
        unsigned ball = __ballot_sync(0xffffffffu, plocal == pbestf);
        int src = __ffs(ball & colmask) - 1;
        int bif = __shfl_sync(0xffffffffu, bi, src);
        if (igrp == 0) sm.back[last][j] = (unsigned char)bif;
    }

    cp_wait<0>();
    __syncthreads();

    // ---- final max / argmax over tags (first occurrence) ----
    if (w == 0) {
        float v  = sm.alpha[p][lane];
        int  idx = lane;
        #pragma unroll
        for (int o = 16; o; o >>= 1) {
            float ov = __shfl_xor_sync(0xffffffffu, v, o);
            int   oi = __shfl_xor_sync(0xffffffffu, idx, o);
            if (ov > v || (ov == v && oi < idx)) { v = ov; idx = oi; }
        }
        if (lane == 0) { out[b] = v; sm.misc[5] = idx; }
    }
    __syncthreads();
    const int last_tag = sm.misc[5];

    float* tags = out + BB + (size_t)b * TT;
    for (int t = len + tid; t < TT; t += NTH) tags[t] = -1.0f;   // PADDING_INDEX

    if (last == 0) {
        if (tid == 0) tags[0] = (float)last_tag;
        return;
    }

    // ---- parallel backtrack: segment-composed pointer chase ----
    const int nseg = (last + LSEG - 1) / LSEG;
    for (int q = tid; q < nseg * NN; q += NTH) {
        const int s  = q >> 5;
        int y        = q & 31;
        const int lo = s * LSEG;
        const int hi = min((s + 1) * LSEG, last);
        for (int t = hi; t > lo; t--) y = sm.back[t][y];
        sm.M[s][q & 31] = (unsigned char)y;   // tag at lo given tag(hi)=x
    }
    __syncthreads();
    if (tid == 0) {
        int cur = last_tag;                   // tag at hi of top segment (== last)
        sm.entry[nseg - 1] = cur;
        for (int s = nseg - 1; s >= 1; s--) {
            cur = sm.M[s][cur];               // tag at lo_s == hi_{s-1}
            sm.entry[s - 1] = cur;
        }
        tags[0] = (float)sm.M[0][cur];        // tag at position 0
    }
    __syncthreads();
    if (tid < nseg) {
        const int s  = tid;
        const int lo = s * LSEG;
        const int hi = min((s + 1) * LSEG, last);
        int cur = sm.entry[s];
        for (int t = hi; t > lo; t--) {
            tags[t] = (float)cur;
            cur = sm.back[t][cur];
        }
    }
}

extern "C" void kernel_launch(void* const* d_in, const int* in_sizes, int n_in,
                              void* d_out, int out_size)
{
    const float* lp   = (const float*)d_in[0];
    const int* mask   = (const int*)d_in[1];
    const int* startc = (const int*)d_in[2];
    const int* endc   = (const int*)d_in[3];
    const int* transc = (const int*)d_in[4];
    float* out = (float*)d_out;
    (void)in_sizes; (void)n_in; (void)out_size;

    const int smem_bytes = (int)sizeof(Smem);   // ~115 KB (< 227 KB limit)
    cudaFuncSetAttribute(viterbi_kernel,
                         cudaFuncAttributeMaxDynamicSharedMemorySize, smem_bytes);
    viterbi_kernel<<<BB, NTH, smem_bytes>>>(lp, mask, startc, endc, transc, out);
}